// round 12
// baseline (speedup 1.0000x reference)
#include <cuda_runtime.h>
#include <stdint.h>

// QueryDepthPoint: depth-constrained radius search.
// B=8, N=16384, M=2048, NSAMPLE=64, DIS_Z=0.5
// SOLVED output format (R1-R10 constraint analysis, zero contradictions):
//   __output__ dtype = FLOAT32. d_out = 1,064,960 f32 = 4,259,840 bytes:
//     idx     (B,M,64) as f32 at elements [0, 1048576)
//     pts_cnt (B,M)    as f32 at elements [1048576, 1064960)
//   (int32 writes read as f32 denormals ~0 -> the repeated exact-1.000000;
//    any footprint > 4,259,840 B faulted.)
// Inputs: float32 xyz1 (B,3,N), xyz2 (B,3,M); exact-size binding + clamps.

#define QB 8
#define QN 16384
#define QM 2048
#define QNS 64
#define QDIS_Z 0.5f

__global__ void __launch_bounds__(256)
qdp_kernel(const float* __restrict__ xyz1, int n1,
           const float* __restrict__ xyz2, int n2,
           float* __restrict__ idx_out,    // f32 values of indices
           float* __restrict__ cnt_out)    // f32 values of counts
{
    const int warp_id = (blockIdx.x * blockDim.x + threadIdx.x) >> 5;
    const int lane = threadIdx.x & 31;
    if (warp_id >= QB * QM) return;
    const int b = warp_id / QM;
    const int m = warp_id - b * QM;

    // Clamped read addressing (mis-bind -> wrong values, never a fault).
    const int z1_base = b * 3 * QN + 2 * QN;
    const float* __restrict__ z1 =
        (z1_base + QN <= n1) ? (xyz1 + z1_base) : xyz1;
    int z2_i = b * 3 * QM + 2 * QM + m;
    if (z2_i >= n2) z2_i = (n2 > 0) ? (n2 - 1) : 0;
    const float z2v = __ldg(&xyz2[z2_i]);

    float* __restrict__ out = idx_out + warp_id * QNS;

    int cnt = 0;          // warp-uniform
    int firstj = 0;       // warp-uniform
    const unsigned full = 0xFFFFFFFFu;
    const unsigned lt_mask = (lane == 0) ? 0u : (0xFFFFFFFFu >> (32 - lane));

    for (int j0 = 0; j0 < QN; j0 += 128) {
        // 4 independent coalesced 128B loads (MLP=4, hides L2 latency)
        float v0 = z1[j0 +  0 + lane];
        float v1 = z1[j0 + 32 + lane];
        float v2 = z1[j0 + 64 + lane];
        float v3 = z1[j0 + 96 + lane];
        unsigned mk0 = __ballot_sync(full, fabsf(v0 - z2v) < QDIS_Z);
        unsigned mk1 = __ballot_sync(full, fabsf(v1 - z2v) < QDIS_Z);
        unsigned mk2 = __ballot_sync(full, fabsf(v2 - z2v) < QDIS_Z);
        unsigned mk3 = __ballot_sync(full, fabsf(v3 - z2v) < QDIS_Z);
        unsigned masks[4] = {mk0, mk1, mk2, mk3};
        #pragma unroll
        for (int c = 0; c < 4; c++) {
            unsigned mk = masks[c];
            if (mk) {   // warp-uniform branch (mk identical across lanes)
                int base = j0 + 32 * c;
                if (cnt == 0) firstj = base + __ffs(mk) - 1;
                int pos = cnt + __popc(mk & lt_mask);
                bool mine = (mk >> lane) & 1u;
                if (mine && pos < QNS)
                    out[pos] = (float)(base + lane);   // exact: values < 2^24
                cnt += __popc(mk);
                if (cnt >= QNS) goto done;   // warp-uniform early exit
            }
        }
    }
done:
    if (cnt > QNS) cnt = QNS;
    // Fill remaining slots with first match (ball-query convention), 0 if none.
    const float fillv = (cnt > 0) ? (float)firstj : 0.0f;
    for (int s = cnt + lane; s < QNS; s += 32)
        out[s] = fillv;
    if (lane == 0)
        cnt_out[warp_id] = (float)cnt;
}

extern "C" void kernel_launch(void* const* d_in, const int* in_sizes, int n_in,
                              void* d_out, int out_size) {
    const int E1 = QB * 3 * QN;   // 393216 elements (xyz1)
    const int E2 = QB * 3 * QM;   // 49152 elements (xyz2)

    // 1) exact size match (element or byte counts)
    const float* xyz1 = nullptr;
    const float* xyz2 = nullptr;
    for (int i = 0; i < n_in; i++) {
        const int sz = in_sizes[i];
        if ((sz == E1 || sz == E1 * 4) && !xyz1) xyz1 = (const float*)d_in[i];
        else if ((sz == E2 || sz == E2 * 4) && !xyz2) xyz2 = (const float*)d_in[i];
    }
    // 2) comparative fallback: larger buffer = xyz1
    if ((!xyz1 || !xyz2) && n_in >= 2) {
        if (in_sizes[0] >= in_sizes[1]) {
            if (!xyz1) xyz1 = (const float*)d_in[0];
            if (!xyz2) xyz2 = (const float*)d_in[1];
        } else {
            if (!xyz1) xyz1 = (const float*)d_in[1];
            if (!xyz2) xyz2 = (const float*)d_in[0];
        }
    }
    if (!xyz1 && n_in >= 1) xyz1 = (const float*)d_in[0];
    if (!xyz2) xyz2 = xyz1;

    // Float32 output layout: idx then pts_cnt (4,259,840 bytes total).
    float* idx_out = (float*)d_out;                  // [0, 1048576)
    float* cnt_out = (float*)d_out + QB * QM * QNS;  // [1048576, 1064960)

    const int total_warps = QB * QM;                 // 16384
    const int threads = 256;
    const int blocks = (total_warps * 32 + threads - 1) / threads;   // 2048
    qdp_kernel<<<blocks, threads>>>(xyz1, E1, xyz2, E2, idx_out, cnt_out);
}

// round 13
// speedup vs baseline: 1.4799x; 1.4799x over previous
#include <cuda_runtime.h>
#include <stdint.h>
#include <math_constants.h>

// QueryDepthPoint: depth-constrained radius search.  B=8, N=16384, M=2048,
// NSAMPLE=64, DIS_Z=0.5.  Output (solved R12): f32 buffer, idx (B,M,64) at
// [0,1048576), pts_cnt (B,M) at [1048576,1064960).
//
// R12 profile: mem ~0%, occ 18.5%, issue 33% -> latency-bound tail (queries
// with |z2|~2.5-3.8 scan up to all 128 iterations serially).
// R13 change: per-128-chunk [min,max] prefilter. 4 ballots build a 128-bit
// candidate-chunk mask; tail queries skip ~85% of chunks, no-match queries
// skip everything. Bulk queries pay ~4 ballots extra.

#define QB 8
#define QN 16384
#define QM 2048
#define QNS 64
#define QDIS_Z 0.5f
#define NCHUNK 128            // chunks of 128 elements per batch row

__device__ float2 g_bounds[QB * NCHUNK];   // [b][chunk] = (min, max) of z1

__global__ void __launch_bounds__(256)
bounds_kernel(const float* __restrict__ xyz1)
{
    const int warp = (blockIdx.x * blockDim.x + threadIdx.x) >> 5;  // 0..1023
    const int lane = threadIdx.x & 31;
    if (warp >= QB * NCHUNK) return;
    const int b = warp >> 7;          // /128
    const int chunk = warp & 127;
    const float* __restrict__ z1 = xyz1 + b * 3 * QN + 2 * QN + chunk * 128;

    float mn =  CUDART_INF_F, mx = -CUDART_INF_F;
    #pragma unroll
    for (int i = 0; i < 4; i++) {
        float v = z1[i * 32 + lane];
        mn = fminf(mn, v);
        mx = fmaxf(mx, v);
    }
    #pragma unroll
    for (int off = 16; off; off >>= 1) {
        mn = fminf(mn, __shfl_xor_sync(0xFFFFFFFFu, mn, off));
        mx = fmaxf(mx, __shfl_xor_sync(0xFFFFFFFFu, mx, off));
    }
    if (lane == 0)
        g_bounds[b * NCHUNK + chunk] = make_float2(mn, mx);
}

__global__ void __launch_bounds__(256)
qdp_kernel(const float* __restrict__ xyz1, int n1,
           const float* __restrict__ xyz2, int n2,
           float* __restrict__ idx_out,
           float* __restrict__ cnt_out)
{
    const int warp_id = (blockIdx.x * blockDim.x + threadIdx.x) >> 5;
    const int lane = threadIdx.x & 31;
    if (warp_id >= QB * QM) return;
    const int b = warp_id / QM;
    const int m = warp_id - b * QM;

    const int z1_base = b * 3 * QN + 2 * QN;
    const float* __restrict__ z1 =
        (z1_base + QN <= n1) ? (xyz1 + z1_base) : xyz1;
    int z2_i = b * 3 * QM + 2 * QM + m;
    if (z2_i >= n2) z2_i = (n2 > 0) ? (n2 - 1) : 0;
    const float z2v = __ldg(&xyz2[z2_i]);

    float* __restrict__ out = idx_out + warp_id * QNS;

    const unsigned full = 0xFFFFFFFFu;
    const unsigned lt_mask = (lane == 0) ? 0u : (0xFFFFFFFFu >> (32 - lane));

    // ---- Candidate-chunk mask: 4 ballots cover 128 chunks ----
    // Widened by 5e-4 so float rounding of (v - z2) can never cause a
    // false skip; false candidates only cost a wasted scan.
    const float2* __restrict__ bnd = g_bounds + b * NCHUNK;
    const float lo = z2v - (QDIS_Z + 5e-4f);
    const float hi = z2v + (QDIS_Z + 5e-4f);
    unsigned cand[4];
    #pragma unroll
    for (int g = 0; g < 4; g++) {
        float2 mb = bnd[g * 32 + lane];
        cand[g] = __ballot_sync(full, (mb.x < hi) && (mb.y > lo));
    }

    int cnt = 0;          // warp-uniform
    int firstj = 0;       // warp-uniform

    #pragma unroll 1
    for (int g = 0; g < 4; g++) {
        unsigned cm = cand[g];
        while (cm) {      // iterate candidate chunks in ascending order
            const int k = __ffs(cm) - 1;
            cm &= cm - 1;
            const int j0 = (g * 32 + k) * 128;

            // 4 independent coalesced 128B loads (MLP=4)
            float v0 = z1[j0 +  0 + lane];
            float v1 = z1[j0 + 32 + lane];
            float v2 = z1[j0 + 64 + lane];
            float v3 = z1[j0 + 96 + lane];
            unsigned mk0 = __ballot_sync(full, fabsf(v0 - z2v) < QDIS_Z);
            unsigned mk1 = __ballot_sync(full, fabsf(v1 - z2v) < QDIS_Z);
            unsigned mk2 = __ballot_sync(full, fabsf(v2 - z2v) < QDIS_Z);
            unsigned mk3 = __ballot_sync(full, fabsf(v3 - z2v) < QDIS_Z);
            unsigned masks[4] = {mk0, mk1, mk2, mk3};
            #pragma unroll
            for (int c = 0; c < 4; c++) {
                unsigned mk = masks[c];
                if (mk) {   // warp-uniform branch
                    int base = j0 + 32 * c;
                    if (cnt == 0) firstj = base + __ffs(mk) - 1;
                    int pos = cnt + __popc(mk & lt_mask);
                    bool mine = (mk >> lane) & 1u;
                    if (mine && pos < QNS)
                        out[pos] = (float)(base + lane);   // exact: < 2^24
                    cnt += __popc(mk);
                    if (cnt >= QNS) goto done;   // warp-uniform early exit
                }
            }
        }
    }
done:
    if (cnt > QNS) cnt = QNS;
    const float fillv = (cnt > 0) ? (float)firstj : 0.0f;
    for (int s = cnt + lane; s < QNS; s += 32)
        out[s] = fillv;
    if (lane == 0)
        cnt_out[warp_id] = (float)cnt;
}

extern "C" void kernel_launch(void* const* d_in, const int* in_sizes, int n_in,
                              void* d_out, int out_size) {
    const int E1 = QB * 3 * QN;   // 393216 elements (xyz1)
    const int E2 = QB * 3 * QM;   // 49152 elements (xyz2)

    const float* xyz1 = nullptr;
    const float* xyz2 = nullptr;
    for (int i = 0; i < n_in; i++) {
        const int sz = in_sizes[i];
        if ((sz == E1 || sz == E1 * 4) && !xyz1) xyz1 = (const float*)d_in[i];
        else if ((sz == E2 || sz == E2 * 4) && !xyz2) xyz2 = (const float*)d_in[i];
    }
    if ((!xyz1 || !xyz2) && n_in >= 2) {
        if (in_sizes[0] >= in_sizes[1]) {
            if (!xyz1) xyz1 = (const float*)d_in[0];
            if (!xyz2) xyz2 = (const float*)d_in[1];
        } else {
            if (!xyz1) xyz1 = (const float*)d_in[1];
            if (!xyz2) xyz2 = (const float*)d_in[0];
        }
    }
    if (!xyz1 && n_in >= 1) xyz1 = (const float*)d_in[0];
    if (!xyz2) xyz2 = xyz1;

    float* idx_out = (float*)d_out;                  // [0, 1048576)
    float* cnt_out = (float*)d_out + QB * QM * QNS;  // [1048576, 1064960)

    // Kernel 1: per-chunk z1 bounds (1024 warps).
    bounds_kernel<<<(QB * NCHUNK * 32 + 255) / 256, 256>>>(xyz1);

    // Kernel 2: query scan with chunk prefilter.
    const int total_warps = QB * QM;                 // 16384
    const int threads = 256;
    const int blocks = (total_warps * 32 + threads - 1) / threads;   // 2048
    qdp_kernel<<<blocks, threads>>>(xyz1, E1, xyz2, E2, idx_out, cnt_out);
}